// round 4
// baseline (speedup 1.0000x reference)
#include <cuda_runtime.h>
#include <cstdint>

// ---------------------------------------------------------------------------
// GIN encoder: 3 x (GINConv(sum-agg) -> MLP(64,relu,64) -> relu -> BN) -> add-pool
// Round 4: tensor-core GEMMs with 3xTF32 error compensation (cuBLAS TF32x3):
//   v = hi + lo (hi = tf32(v), lo = tf32(v - hi));  A*B ~= Ah*Bh + Ah*Bl + Al*Bh
//   -> ~2^-22 effective precision, fp32-class accuracy at tensor-core speed.
//   * CSR built per call (init -> hist -> scan -> fill)
//   * fused kernel per layer: gather (1 warp / 8 nodes, CSR, prev-layer BN
//     affine folded in) -> GEMM1 -> relu -> GEMM2 -> relu -> store + BN stats
//   * smem (dynamic, 68KB): As hi/lo + Ws hi/lo, PAD=68 => conflict-free
//   * pool: sorted-batch run-length accumulation
// ---------------------------------------------------------------------------

#define MAXN 131072
#define MAXE 2200000
#define PAD  68
#define TILE_WORDS (64 * PAD)
#define DYN_BYTES  (4 * TILE_WORDS * 4)

__device__ int   g_deg[MAXN];
__device__ int   g_cursor[MAXN];
__device__ int   g_rowptr[MAXN + 1];
__device__ int   g_col[MAXE];
__device__ int   g_bsum[1024];
__device__ float g_rA[(size_t)MAXN * 64];
__device__ float g_rB[(size_t)MAXN * 64];
__device__ float g_stats[3 * 128];   // per layer: [0:64) sum, [64:128) sumsq
__device__ float g_coef[3 * 128];    // per layer: [0:64) scale a, [64:128) shift b

__device__ __forceinline__ uint32_t f2tf32(float f) {
    uint32_t r;
    asm("cvt.rna.tf32.f32 %0, %1;" : "=r"(r) : "f"(f));
    return r;
}

// split v into tf32 hi + tf32 lo
__device__ __forceinline__ void tf32split(float v, uint32_t& hi, uint32_t& lo) {
    hi = f2tf32(v);
    lo = f2tf32(v - __uint_as_float(hi));
}

__device__ __forceinline__ void mma_tf32(float c[4],
    uint32_t a0, uint32_t a1, uint32_t a2, uint32_t a3,
    uint32_t b0, uint32_t b1)
{
    asm volatile(
        "mma.sync.aligned.m16n8k8.row.col.f32.tf32.tf32.f32 "
        "{%0,%1,%2,%3}, {%4,%5,%6,%7}, {%8,%9}, {%0,%1,%2,%3};"
        : "+f"(c[0]), "+f"(c[1]), "+f"(c[2]), "+f"(c[3])
        : "r"(a0), "r"(a1), "r"(a2), "r"(a3), "r"(b0), "r"(b1));
}

// ---------------------------- init + CSR build ----------------------------

__global__ void k_init(int N) {
    int i = blockIdx.x * blockDim.x + threadIdx.x;
    if (i < N) { g_deg[i] = 0; g_cursor[i] = 0; }
    if (i < 384) g_stats[i] = 0.f;
}

__global__ void k_hist(const int* __restrict__ dst, int E) {
    int e = blockIdx.x * blockDim.x + threadIdx.x;
    if (e < E) atomicAdd(&g_deg[dst[e]], 1);
}

__global__ void k_scan1(int N) {
    __shared__ int wsum[32];
    int t    = threadIdx.x;            // 1024 threads
    int idx  = blockIdx.x * 1024 + t;
    int v    = (idx < N) ? g_deg[idx] : 0;
    int lane = t & 31, w = t >> 5;
    int inc  = v;
#pragma unroll
    for (int o = 1; o < 32; o <<= 1) {
        int nn = __shfl_up_sync(0xffffffffu, inc, o);
        if (lane >= o) inc += nn;
    }
    if (lane == 31) wsum[w] = inc;
    __syncthreads();
    if (w == 0) {
        int s = wsum[lane];
#pragma unroll
        for (int o = 1; o < 32; o <<= 1) {
            int nn = __shfl_up_sync(0xffffffffu, s, o);
            if (lane >= o) s += nn;
        }
        wsum[lane] = s;
    }
    __syncthreads();
    int excl = inc - v + (w > 0 ? wsum[w - 1] : 0);
    if (idx < N) g_rowptr[idx] = excl;
    if (t == 0) g_bsum[blockIdx.x] = wsum[31];
}

__global__ void k_scan2(int B) {
    __shared__ int wsum[32];
    int t    = threadIdx.x;  // 1024
    int v    = (t < B) ? g_bsum[t] : 0;
    int lane = t & 31, w = t >> 5;
    int inc  = v;
#pragma unroll
    for (int o = 1; o < 32; o <<= 1) {
        int nn = __shfl_up_sync(0xffffffffu, inc, o);
        if (lane >= o) inc += nn;
    }
    if (lane == 31) wsum[w] = inc;
    __syncthreads();
    if (w == 0) {
        int s = wsum[lane];
#pragma unroll
        for (int o = 1; o < 32; o <<= 1) {
            int nn = __shfl_up_sync(0xffffffffu, s, o);
            if (lane >= o) s += nn;
        }
        wsum[lane] = s;
    }
    __syncthreads();
    int excl = inc - v + (w > 0 ? wsum[w - 1] : 0);
    if (t < B) g_bsum[t] = excl;
}

__global__ void k_scan3(int N, int E) {
    int idx = blockIdx.x * blockDim.x + threadIdx.x;
    if (idx < N)       g_rowptr[idx] += g_bsum[idx >> 10];
    else if (idx == N) g_rowptr[N] = E;
}

__global__ void k_fill(const int* __restrict__ src, const int* __restrict__ dst, int E) {
    int e = blockIdx.x * blockDim.x + threadIdx.x;
    if (e < E) {
        int d = dst[e];
        int p = atomicAdd(&g_cursor[d], 1);
        g_col[g_rowptr[d] + p] = src[e];
    }
}

// ---------- fused gather + 3xTF32 tensor-core MLP + relu + BN stats --------
// 64-node tile per block, 256 threads (8 warps). Warp tile m16 x n32.
__global__ __launch_bounds__(256) void k_fused(
    const float* __restrict__ x, int insel /*0=x,1=rA,2=rB*/, int layer,
    const float* __restrict__ wa, const float* __restrict__ ba,
    const float* __restrict__ wb, const float* __restrict__ bb,
    int outsel /*1=g_rA, 2=g_rB*/, int N)
{
    extern __shared__ uint32_t dyn[];
    uint32_t* AsH = dyn;
    uint32_t* AsL = dyn + TILE_WORDS;
    uint32_t* WsH = dyn + 2 * TILE_WORDS;
    uint32_t* WsL = dyn + 3 * TILE_WORDS;
    __shared__ float B1s[64], B2s[64];
    __shared__ float ssum[64], ssq[64];

    float* r = (outsel == 1) ? g_rA : g_rB;
    int t    = threadIdx.x;
    int warp = t >> 5;
    int lane = t & 31;
    int m0   = blockIdx.x * 64;

    // load W1 transposed to [n][k] (hi/lo) + biases + init stats
#pragma unroll
    for (int i = 0; i < 16; i++) {
        int idx = t + 256 * i;       // 0..4095
        int k = idx >> 6, n = idx & 63;
        uint32_t hi, lo;
        tf32split(wa[idx], hi, lo);
        WsH[n * PAD + k] = hi;
        WsL[n * PAD + k] = lo;
    }
    if (t < 64) { B1s[t] = ba[t]; B2s[t] = bb[t]; ssum[t] = 0.f; ssq[t] = 0.f; }

    // ---- Phase A: gather (self + CSR neighbor sum, prev BN affine) ----
    const float* in = (insel == 0) ? x : (insel == 1 ? g_rA : g_rB);
    const float2* inp = (const float2*)in;

    float a0c = 1.f, a1c = 1.f, b0c = 0.f, b1c = 0.f;
    if (layer > 0) {
        const float* cf = &g_coef[(layer - 1) * 128];
        a0c = cf[2 * lane];      a1c = cf[2 * lane + 1];
        b0c = cf[64 + 2 * lane]; b1c = cf[65 + 2 * lane];
    }

#pragma unroll 1
    for (int i = 0; i < 8; i++) {
        int row  = warp * 8 + i;
        int node = m0 + row;
        float2 acc = make_float2(0.f, 0.f);
        if (node < N) {
            acc = inp[node * 32 + lane];  // self term
            int beg = g_rowptr[node], end = g_rowptr[node + 1];
            int e = beg;
            for (; e + 3 < end; e += 4) {
                int s0 = g_col[e], s1 = g_col[e + 1];
                int s2 = g_col[e + 2], s3 = g_col[e + 3];
                float2 v0 = inp[s0 * 32 + lane];
                float2 v1 = inp[s1 * 32 + lane];
                float2 v2 = inp[s2 * 32 + lane];
                float2 v3 = inp[s3 * 32 + lane];
                acc.x += (v0.x + v1.x) + (v2.x + v3.x);
                acc.y += (v0.y + v1.y) + (v2.y + v3.y);
            }
            for (; e < end; e++) {
                float2 v = inp[g_col[e] * 32 + lane];
                acc.x += v.x;
                acc.y += v.y;
            }
            if (layer > 0) {
                float cnt = (float)(end - beg + 1);
                acc.x = a0c * acc.x + cnt * b0c;
                acc.y = a1c * acc.y + cnt * b1c;
            }
        }
        uint32_t hx, lx, hy, ly;
        tf32split(acc.x, hx, lx);
        tf32split(acc.y, hy, ly);
        *(uint2*)&AsH[row * PAD + 2 * lane] = make_uint2(hx, hy);
        *(uint2*)&AsL[row * PAD + 2 * lane] = make_uint2(lx, ly);
    }
    __syncthreads();

    // ---- Phase B: tensor-core GEMMs (3xTF32) ----
    int gid = lane >> 2, tig = lane & 3;   // groupID, threadID-in-group
    int mi  = warp & 3,  ni  = warp >> 2;  // warp tile: rows mi*16, cols ni*32

    int aoff = (mi * 16 + gid) * PAD + tig;
    int boff = (ni * 32 + gid) * PAD + tig;

    float c[4][4];
#pragma unroll
    for (int nt = 0; nt < 4; nt++)
#pragma unroll
        for (int j = 0; j < 4; j++) c[nt][j] = 0.f;

    // GEMM1
#pragma unroll
    for (int kt = 0; kt < 8; kt++) {
        uint32_t ah0 = AsH[aoff + kt * 8];
        uint32_t ah1 = AsH[aoff + kt * 8 + 8 * PAD];
        uint32_t ah2 = AsH[aoff + kt * 8 + 4];
        uint32_t ah3 = AsH[aoff + kt * 8 + 8 * PAD + 4];
        uint32_t al0 = AsL[aoff + kt * 8];
        uint32_t al1 = AsL[aoff + kt * 8 + 8 * PAD];
        uint32_t al2 = AsL[aoff + kt * 8 + 4];
        uint32_t al3 = AsL[aoff + kt * 8 + 8 * PAD + 4];
#pragma unroll
        for (int nt = 0; nt < 4; nt++) {
            uint32_t bh0 = WsH[boff + nt * 8 * PAD + kt * 8];
            uint32_t bh1 = WsH[boff + nt * 8 * PAD + kt * 8 + 4];
            uint32_t bl0 = WsL[boff + nt * 8 * PAD + kt * 8];
            uint32_t bl1 = WsL[boff + nt * 8 * PAD + kt * 8 + 4];
            mma_tf32(c[nt], ah0, ah1, ah2, ah3, bh0, bh1);
            mma_tf32(c[nt], ah0, ah1, ah2, ah3, bl0, bl1);
            mma_tf32(c[nt], al0, al1, al2, al3, bh0, bh1);
        }
    }
    __syncthreads();  // all reads of As (A) and Ws (W1) done

    // h = relu(c + b1) -> As (becomes A of GEMM2); reload Ws with W2
#pragma unroll
    for (int nt = 0; nt < 4; nt++) {
        int n0 = ni * 32 + nt * 8 + 2 * tig;
        float bb0 = B1s[n0], bb1 = B1s[n0 + 1];
        int r0 = mi * 16 + gid;
        float v00 = fmaxf(c[nt][0] + bb0, 0.f);
        float v01 = fmaxf(c[nt][1] + bb1, 0.f);
        float v10 = fmaxf(c[nt][2] + bb0, 0.f);
        float v11 = fmaxf(c[nt][3] + bb1, 0.f);
        uint32_t h00, l00, h01, l01, h10, l10, h11, l11;
        tf32split(v00, h00, l00);
        tf32split(v01, h01, l01);
        tf32split(v10, h10, l10);
        tf32split(v11, h11, l11);
        *(uint2*)&AsH[r0 * PAD + n0]       = make_uint2(h00, h01);
        *(uint2*)&AsL[r0 * PAD + n0]       = make_uint2(l00, l01);
        *(uint2*)&AsH[(r0 + 8) * PAD + n0] = make_uint2(h10, h11);
        *(uint2*)&AsL[(r0 + 8) * PAD + n0] = make_uint2(l10, l11);
#pragma unroll
        for (int j = 0; j < 4; j++) c[nt][j] = 0.f;
    }
#pragma unroll
    for (int i = 0; i < 16; i++) {
        int idx = t + 256 * i;
        int k = idx >> 6, n = idx & 63;
        uint32_t hi, lo;
        tf32split(wb[idx], hi, lo);
        WsH[n * PAD + k] = hi;
        WsL[n * PAD + k] = lo;
    }
    __syncthreads();

    // GEMM2
#pragma unroll
    for (int kt = 0; kt < 8; kt++) {
        uint32_t ah0 = AsH[aoff + kt * 8];
        uint32_t ah1 = AsH[aoff + kt * 8 + 8 * PAD];
        uint32_t ah2 = AsH[aoff + kt * 8 + 4];
        uint32_t ah3 = AsH[aoff + kt * 8 + 8 * PAD + 4];
        uint32_t al0 = AsL[aoff + kt * 8];
        uint32_t al1 = AsL[aoff + kt * 8 + 8 * PAD];
        uint32_t al2 = AsL[aoff + kt * 8 + 4];
        uint32_t al3 = AsL[aoff + kt * 8 + 8 * PAD + 4];
#pragma unroll
        for (int nt = 0; nt < 4; nt++) {
            uint32_t bh0 = WsH[boff + nt * 8 * PAD + kt * 8];
            uint32_t bh1 = WsH[boff + nt * 8 * PAD + kt * 8 + 4];
            uint32_t bl0 = WsL[boff + nt * 8 * PAD + kt * 8];
            uint32_t bl1 = WsL[boff + nt * 8 * PAD + kt * 8 + 4];
            mma_tf32(c[nt], ah0, ah1, ah2, ah3, bh0, bh1);
            mma_tf32(c[nt], ah0, ah1, ah2, ah3, bl0, bl1);
            mma_tf32(c[nt], al0, al1, al2, al3, bh0, bh1);
        }
    }

    // epilogue: relu, store, BN stats
#pragma unroll
    for (int nt = 0; nt < 4; nt++) {
        int n0 = ni * 32 + nt * 8 + 2 * tig;
        float bb0 = B2s[n0], bb1 = B2s[n0 + 1];
        int r0 = m0 + mi * 16 + gid;
        float v00 = fmaxf(c[nt][0] + bb0, 0.f);
        float v01 = fmaxf(c[nt][1] + bb1, 0.f);
        float v10 = fmaxf(c[nt][2] + bb0, 0.f);
        float v11 = fmaxf(c[nt][3] + bb1, 0.f);
        float s0 = 0.f, q0 = 0.f, s1 = 0.f, q1 = 0.f;
        if (r0 < N) {
            *(float2*)&r[(size_t)r0 * 64 + n0] = make_float2(v00, v01);
            s0 += v00; q0 += v00 * v00;
            s1 += v01; q1 += v01 * v01;
        }
        if (r0 + 8 < N) {
            *(float2*)&r[(size_t)(r0 + 8) * 64 + n0] = make_float2(v10, v11);
            s0 += v10; q0 += v10 * v10;
            s1 += v11; q1 += v11 * v11;
        }
        atomicAdd(&ssum[n0], s0);     atomicAdd(&ssq[n0], q0);
        atomicAdd(&ssum[n0 + 1], s1); atomicAdd(&ssq[n0 + 1], q1);
    }
    __syncthreads();
    if (t < 64) {
        atomicAdd(&g_stats[layer * 128 + t],      ssum[t]);
        atomicAdd(&g_stats[layer * 128 + 64 + t], ssq[t]);
    }
}

// ---------------------------- BN finalize ---------------------------------
__global__ void k_bnfin(const float* __restrict__ gamma,
                        const float* __restrict__ beta, int layer, int N) {
    int t = threadIdx.x;  // 64
    if (t >= 64) return;
    float invN = 1.f / (float)N;
    float mean = g_stats[layer * 128 + t] * invN;
    float var  = g_stats[layer * 128 + 64 + t] * invN - mean * mean;
    var = fmaxf(var, 0.f);
    float s = gamma[t] * rsqrtf(var + 1e-5f);
    g_coef[layer * 128 + t]      = s;
    g_coef[layer * 128 + 64 + t] = beta[t] - mean * s;
}

// ---------------------------- pool -----------------------------------------
__global__ void k_pool(int insel /*1=g_rA, 2=g_rB*/, const int* __restrict__ batch,
                       float* __restrict__ out, int N) {
    const float* r = (insel == 1) ? g_rA : g_rB;
    const float* cf = &g_coef[2 * 128];
    int t   = threadIdx.x;  // 256
    int f   = t & 63;
    int sub = t >> 6;       // 0..3
    float a = cf[f], b = cf[64 + f];
    int n0  = blockIdx.x * 128;
    int nend = min(n0 + 128, N);
    float acc = 0.f;
    int curg = -1;
    for (int n = n0 + sub; n < nend; n += 4) {
        int g = batch[n];
        if (g != curg) {
            if (curg >= 0) atomicAdd(&out[curg * 64 + f], acc);
            curg = g;
            acc = 0.f;
        }
        acc += a * r[(size_t)n * 64 + f] + b;
    }
    if (curg >= 0) atomicAdd(&out[curg * 64 + f], acc);
}

// ---------------------------- launch ---------------------------------------
extern "C" void kernel_launch(void* const* d_in, const int* in_sizes, int n_in,
                              void* d_out, int out_size) {
    const float* x     = (const float*)d_in[0];
    const int*   ei    = (const int*)d_in[1];
    const int*   batch = (const int*)d_in[2];

    const float* WA[3] = {(const float*)d_in[3],  (const float*)d_in[9],  (const float*)d_in[15]};
    const float* BA[3] = {(const float*)d_in[4],  (const float*)d_in[10], (const float*)d_in[16]};
    const float* WB[3] = {(const float*)d_in[5],  (const float*)d_in[11], (const float*)d_in[17]};
    const float* BB[3] = {(const float*)d_in[6],  (const float*)d_in[12], (const float*)d_in[18]};
    const float* GM[3] = {(const float*)d_in[7],  (const float*)d_in[13], (const float*)d_in[19]};
    const float* BE[3] = {(const float*)d_in[8],  (const float*)d_in[14], (const float*)d_in[20]};

    int N = in_sizes[0] / 64;
    int E = in_sizes[1] / 2;
    const int* src = ei;
    const int* dst = ei + E;

    cudaFuncSetAttribute(k_fused, cudaFuncAttributeMaxDynamicSharedMemorySize,
                         DYN_BYTES);

    // CSR build
    k_init<<<(N + 255) / 256, 256>>>(N);
    k_hist<<<(E + 255) / 256, 256>>>(dst, E);
    int sb = (N + 1023) / 1024;
    k_scan1<<<sb, 1024>>>(N);
    k_scan2<<<1, 1024>>>(sb);
    k_scan3<<<(N + 1 + 255) / 256, 256>>>(N, E);
    k_fill<<<(E + 255) / 256, 256>>>(src, dst, E);

    // 3 GIN layers, fused gather + 3xTF32 tensor-core MLP; ping-pong rA/rB
    int insel = 0;  // x
    for (int L = 0; L < 3; L++) {
        int outsel = (L & 1) ? 2 : 1;  // L0->rA, L1->rB, L2->rA
        k_fused<<<(N + 63) / 64, 256, DYN_BYTES>>>(x, insel, L,
                                        WA[L], BA[L], WB[L], BB[L], outsel, N);
        k_bnfin<<<1, 64>>>(GM[L], BE[L], L, N);
        insel = outsel;
    }

    cudaMemsetAsync(d_out, 0, (size_t)out_size * sizeof(float));
    k_pool<<<(N + 127) / 128, 256>>>(insel, batch, (float*)d_out, N);
}

// round 5
// speedup vs baseline: 1.4636x; 1.4636x over previous
#include <cuda_runtime.h>
#include <cuda_bf16.h>
#include <cstdint>

// ---------------------------------------------------------------------------
// GIN encoder: 3 x (GINConv(sum-agg) -> MLP(64,relu,64) -> relu -> BN) -> add-pool
// Round 5: tensor-core GEMMs via bf16 m16n8k16 with 3-term error compensation:
//   v = hi + lo (bf16 each); A*B ~= Ah*Bh + Ah*Bl + Al*Bh  (~2^-16 / product)
//   hi/lo bf16 pairs pack 2 values per 32-bit word -> smem back to ~37KB static,
//   restoring the occupancy the tf32x3 version lost (its 68KB -> 3 blocks/SM).
//   * CSR built per call (init -> hist -> scan -> fill)
//   * fused kernel per layer: gather (1 warp / 8 nodes, CSR, prev-layer BN
//     affine folded in) -> GEMM1 -> relu -> GEMM2 -> relu -> store + BN stats
//   * pitch-36 smem => conflict-free fragment loads/stores
//   * pool: sorted-batch run-length accumulation
// ---------------------------------------------------------------------------

#define MAXN 131072
#define MAXE 2200000
#define KP   36              // pitch in packed (2xbf16) words per 64-row

__device__ int   g_deg[MAXN];
__device__ int   g_cursor[MAXN];
__device__ int   g_rowptr[MAXN + 1];
__device__ int   g_col[MAXE];
__device__ int   g_bsum[1024];
__device__ float g_rA[(size_t)MAXN * 64];
__device__ float g_rB[(size_t)MAXN * 64];
__device__ float g_stats[3 * 128];   // per layer: [0:64) sum, [64:128) sumsq
__device__ float g_coef[3 * 128];    // per layer: [0:64) scale a, [64:128) shift b

__device__ __forceinline__ uint32_t pack_bf16(float a, float b) {
    __nv_bfloat162 p;
    p.x = __float2bfloat16_rn(a);
    p.y = __float2bfloat16_rn(b);
    return *(uint32_t*)&p;
}

// split (a,b) into packed bf16 hi word and lo word
__device__ __forceinline__ void bf16split2(float a, float b,
                                           uint32_t& hi, uint32_t& lo) {
    __nv_bfloat16 ha = __float2bfloat16_rn(a);
    __nv_bfloat16 hb = __float2bfloat16_rn(b);
    float la = a - __bfloat162float(ha);
    float lb = b - __bfloat162float(hb);
    __nv_bfloat162 ph, pl;
    ph.x = ha; ph.y = hb;
    pl.x = __float2bfloat16_rn(la); pl.y = __float2bfloat16_rn(lb);
    hi = *(uint32_t*)&ph;
    lo = *(uint32_t*)&pl;
}

__device__ __forceinline__ void mma_bf16(float c[4],
    uint32_t a0, uint32_t a1, uint32_t a2, uint32_t a3,
    uint32_t b0, uint32_t b1)
{
    asm volatile(
        "mma.sync.aligned.m16n8k16.row.col.f32.bf16.bf16.f32 "
        "{%0,%1,%2,%3}, {%4,%5,%6,%7}, {%8,%9}, {%0,%1,%2,%3};"
        : "+f"(c[0]), "+f"(c[1]), "+f"(c[2]), "+f"(c[3])
        : "r"(a0), "r"(a1), "r"(a2), "r"(a3), "r"(b0), "r"(b1));
}

// ---------------------------- init + CSR build ----------------------------

__global__ void k_init(int N) {
    int i = blockIdx.x * blockDim.x + threadIdx.x;
    if (i < N) { g_deg[i] = 0; g_cursor[i] = 0; }
    if (i < 384) g_stats[i] = 0.f;
}

__global__ void k_hist(const int* __restrict__ dst, int E) {
    int e = blockIdx.x * blockDim.x + threadIdx.x;
    if (e < E) atomicAdd(&g_deg[dst[e]], 1);
}

__global__ void k_scan1(int N) {
    __shared__ int wsum[32];
    int t    = threadIdx.x;            // 1024 threads
    int idx  = blockIdx.x * 1024 + t;
    int v    = (idx < N) ? g_deg[idx] : 0;
    int lane = t & 31, w = t >> 5;
    int inc  = v;
#pragma unroll
    for (int o = 1; o < 32; o <<= 1) {
        int nn = __shfl_up_sync(0xffffffffu, inc, o);
        if (lane >= o) inc += nn;
    }
    if (lane == 31) wsum[w] = inc;
    __syncthreads();
    if (w == 0) {
        int s = wsum[lane];
#pragma unroll
        for (int o = 1; o < 32; o <<= 1) {
            int nn = __shfl_up_sync(0xffffffffu, s, o);
            if (lane >= o) s += nn;
        }
        wsum[lane] = s;
    }
    __syncthreads();
    int excl = inc - v + (w > 0 ? wsum[w - 1] : 0);
    if (idx < N) g_rowptr[idx] = excl;
    if (t == 0) g_bsum[blockIdx.x] = wsum[31];
}

__global__ void k_scan2(int B) {
    __shared__ int wsum[32];
    int t    = threadIdx.x;  // 1024
    int v    = (t < B) ? g_bsum[t] : 0;
    int lane = t & 31, w = t >> 5;
    int inc  = v;
#pragma unroll
    for (int o = 1; o < 32; o <<= 1) {
        int nn = __shfl_up_sync(0xffffffffu, inc, o);
        if (lane >= o) inc += nn;
    }
    if (lane == 31) wsum[w] = inc;
    __syncthreads();
    if (w == 0) {
        int s = wsum[lane];
#pragma unroll
        for (int o = 1; o < 32; o <<= 1) {
            int nn = __shfl_up_sync(0xffffffffu, s, o);
            if (lane >= o) s += nn;
        }
        wsum[lane] = s;
    }
    __syncthreads();
    int excl = inc - v + (w > 0 ? wsum[w - 1] : 0);
    if (t < B) g_bsum[t] = excl;
}

__global__ void k_scan3(int N, int E) {
    int idx = blockIdx.x * blockDim.x + threadIdx.x;
    if (idx < N)       g_rowptr[idx] += g_bsum[idx >> 10];
    else if (idx == N) g_rowptr[N] = E;
}

__global__ void k_fill(const int* __restrict__ src, const int* __restrict__ dst, int E) {
    int e = blockIdx.x * blockDim.x + threadIdx.x;
    if (e < E) {
        int d = dst[e];
        int p = atomicAdd(&g_cursor[d], 1);
        g_col[g_rowptr[d] + p] = src[e];
    }
}

// ---------- fused gather + bf16x3 tensor-core MLP + relu + BN stats --------
// 64-node tile per block, 256 threads (8 warps). Warp tile m16 x n32.
// Packed smem: X[row][kp] holds bf16 pair (feat 2kp, 2kp+1); pitch KP=36
// => (4*row + idx) mod 32 patterns are conflict-free everywhere.
__global__ __launch_bounds__(256) void k_fused(
    const float* __restrict__ x, int insel /*0=x,1=rA,2=rB*/, int layer,
    const float* __restrict__ wa, const float* __restrict__ ba,
    const float* __restrict__ wb, const float* __restrict__ bb,
    int outsel /*1=g_rA, 2=g_rB*/, int N)
{
    __shared__ uint32_t PH[64 * KP];   // A hi (agg, then h)
    __shared__ uint32_t PL[64 * KP];   // A lo
    __shared__ uint32_t QH[64 * KP];   // W hi, [n][kp]
    __shared__ uint32_t QL[64 * KP];   // W lo
    __shared__ float B1s[64], B2s[64];
    __shared__ float ssum[64], ssq[64];

    float* r = (outsel == 1) ? g_rA : g_rB;
    int t    = threadIdx.x;
    int warp = t >> 5;
    int lane = t & 31;
    int m0   = blockIdx.x * 64;

    // load W1 -> QH/QL as [n][kp] (kp packs k=2kp,2kp+1); coalesced reads
#pragma unroll
    for (int i = 0; i < 8; i++) {
        int idx = t + 256 * i;       // 0..2047
        int n = idx & 63, kp = idx >> 6;
        uint32_t hi, lo;
        bf16split2(wa[(2 * kp) * 64 + n], wa[(2 * kp + 1) * 64 + n], hi, lo);
        QH[n * KP + kp] = hi;
        QL[n * KP + kp] = lo;
    }
    if (t < 64) { B1s[t] = ba[t]; B2s[t] = bb[t]; ssum[t] = 0.f; ssq[t] = 0.f; }

    // ---- Phase A: gather (self + CSR neighbor sum, prev BN affine) ----
    const float* in = (insel == 0) ? x : (insel == 1 ? g_rA : g_rB);
    const float2* inp = (const float2*)in;

    float a0c = 1.f, a1c = 1.f, b0c = 0.f, b1c = 0.f;
    if (layer > 0) {
        const float* cf = &g_coef[(layer - 1) * 128];
        a0c = cf[2 * lane];      a1c = cf[2 * lane + 1];
        b0c = cf[64 + 2 * lane]; b1c = cf[65 + 2 * lane];
    }

#pragma unroll 1
    for (int i = 0; i < 8; i++) {
        int row  = warp * 8 + i;
        int node = m0 + row;
        float2 acc = make_float2(0.f, 0.f);
        if (node < N) {
            acc = inp[node * 32 + lane];  // self term
            int beg = g_rowptr[node], end = g_rowptr[node + 1];
            int e = beg;
            for (; e + 3 < end; e += 4) {
                int s0 = g_col[e], s1 = g_col[e + 1];
                int s2 = g_col[e + 2], s3 = g_col[e + 3];
                float2 v0 = inp[s0 * 32 + lane];
                float2 v1 = inp[s1 * 32 + lane];
                float2 v2 = inp[s2 * 32 + lane];
                float2 v3 = inp[s3 * 32 + lane];
                acc.x += (v0.x + v1.x) + (v2.x + v3.x);
                acc.y += (v0.y + v1.y) + (v2.y + v3.y);
            }
            for (; e < end; e++) {
                float2 v = inp[g_col[e] * 32 + lane];
                acc.x += v.x;
                acc.y += v.y;
            }
            if (layer > 0) {
                float cnt = (float)(end - beg + 1);
                acc.x = a0c * acc.x + cnt * b0c;
                acc.y = a1c * acc.y + cnt * b1c;
            }
        }
        uint32_t hi, lo;
        bf16split2(acc.x, acc.y, hi, lo);   // lane owns feats 2*lane, 2*lane+1
        PH[row * KP + lane] = hi;
        PL[row * KP + lane] = lo;
    }
    __syncthreads();

    // ---- Phase B: tensor-core GEMMs (bf16 x3) ----
    int gid = lane >> 2, tig = lane & 3;   // groupID, threadID-in-group
    int mi  = warp & 3,  ni  = warp >> 2;  // warp tile: rows mi*16, cols ni*32

    int aoff = (mi * 16 + gid) * KP + tig;
    int boff = (ni * 32 + gid) * KP + tig;

    float c[4][4];
#pragma unroll
    for (int nt = 0; nt < 4; nt++)
#pragma unroll
        for (int j = 0; j < 4; j++) c[nt][j] = 0.f;

    // GEMM1: 4 k-steps of 16
#pragma unroll
    for (int kt = 0; kt < 4; kt++) {
        uint32_t ah0 = PH[aoff + kt * 8];
        uint32_t ah1 = PH[aoff + kt * 8 + 8 * KP];
        uint32_t ah2 = PH[aoff + kt * 8 + 4];
        uint32_t ah3 = PH[aoff + kt * 8 + 8 * KP + 4];
        uint32_t al0 = PL[aoff + kt * 8];
        uint32_t al1 = PL[aoff + kt * 8 + 8 * KP];
        uint32_t al2 = PL[aoff + kt * 8 + 4];
        uint32_t al3 = PL[aoff + kt * 8 + 8 * KP + 4];
#pragma unroll
        for (int nt = 0; nt < 4; nt++) {
            uint32_t bh0 = QH[boff + nt * 8 * KP + kt * 8];
            uint32_t bh1 = QH[boff + nt * 8 * KP + kt * 8 + 4];
            uint32_t bl0 = QL[boff + nt * 8 * KP + kt * 8];
            uint32_t bl1 = QL[boff + nt * 8 * KP + kt * 8 + 4];
            mma_bf16(c[nt], ah0, ah1, ah2, ah3, bh0, bh1);
            mma_bf16(c[nt], ah0, ah1, ah2, ah3, bl0, bl1);
            mma_bf16(c[nt], al0, al1, al2, al3, bh0, bh1);
        }
    }
    __syncthreads();  // all reads of PH/PL (A) and QH/QL (W1) done

    // h = relu(c + b1) -> PH/PL (A of GEMM2); reload QH/QL with W2
#pragma unroll
    for (int nt = 0; nt < 4; nt++) {
        int n0 = ni * 32 + nt * 8 + 2 * tig;
        float bb0 = B1s[n0], bb1 = B1s[n0 + 1];
        int r0 = mi * 16 + gid;
        int kp = (n0 >> 1);                  // = ni*16 + nt*4 + tig
        uint32_t hi, lo;
        bf16split2(fmaxf(c[nt][0] + bb0, 0.f), fmaxf(c[nt][1] + bb1, 0.f), hi, lo);
        PH[r0 * KP + kp] = hi;
        PL[r0 * KP + kp] = lo;
        bf16split2(fmaxf(c[nt][2] + bb0, 0.f), fmaxf(c[nt][3] + bb1, 0.f), hi, lo);
        PH[(r0 + 8) * KP + kp] = hi;
        PL[(r0 + 8) * KP + kp] = lo;
#pragma unroll
        for (int j = 0; j < 4; j++) c[nt][j] = 0.f;
    }
#pragma unroll
    for (int i = 0; i < 8; i++) {
        int idx = t + 256 * i;
        int n = idx & 63, kp = idx >> 6;
        uint32_t hi, lo;
        bf16split2(wb[(2 * kp) * 64 + n], wb[(2 * kp + 1) * 64 + n], hi, lo);
        QH[n * KP + kp] = hi;
        QL[n * KP + kp] = lo;
    }
    __syncthreads();

    // GEMM2
#pragma unroll
    for (int kt = 0; kt < 4; kt++) {
        uint32_t ah0 = PH[aoff + kt * 8];
        uint32_t ah1 = PH[aoff + kt * 8 + 8 * KP];
        uint32_t ah2 = PH[aoff + kt * 8 + 4];
        uint32_t ah3 = PH[aoff + kt * 8 + 8 * KP + 4];
        uint32_t al0 = PL[aoff + kt * 8];
        uint32_t al1 = PL[aoff + kt * 8 + 8 * KP];
        uint32_t al2 = PL[aoff + kt * 8 + 4];
        uint32_t al3 = PL[aoff + kt * 8 + 8 * KP + 4];
#pragma unroll
        for (int nt = 0; nt < 4; nt++) {
            uint32_t bh0 = QH[boff + nt * 8 * KP + kt * 8];
            uint32_t bh1 = QH[boff + nt * 8 * KP + kt * 8 + 4];
            uint32_t bl0 = QL[boff + nt * 8 * KP + kt * 8];
            uint32_t bl1 = QL[boff + nt * 8 * KP + kt * 8 + 4];
            mma_bf16(c[nt], ah0, ah1, ah2, ah3, bh0, bh1);
            mma_bf16(c[nt], ah0, ah1, ah2, ah3, bl0, bl1);
            mma_bf16(c[nt], al0, al1, al2, al3, bh0, bh1);
        }
    }

    // epilogue: relu, store, BN stats
#pragma unroll
    for (int nt = 0; nt < 4; nt++) {
        int n0 = ni * 32 + nt * 8 + 2 * tig;
        float bb0 = B2s[n0], bb1 = B2s[n0 + 1];
        int r0 = m0 + mi * 16 + gid;
        float v00 = fmaxf(c[nt][0] + bb0, 0.f);
        float v01 = fmaxf(c[nt][1] + bb1, 0.f);
        float v10 = fmaxf(c[nt][2] + bb0, 0.f);
        float v11 = fmaxf(c[nt][3] + bb1, 0.f);
        float s0 = 0.f, q0 = 0.f, s1 = 0.f, q1 = 0.f;
        if (r0 < N) {
            *(float2*)&r[(size_t)r0 * 64 + n0] = make_float2(v00, v01);
            s0 += v00; q0 += v00 * v00;
            s1 += v01; q1 += v01 * v01;
        }
        if (r0 + 8 < N) {
            *(float2*)&r[(size_t)(r0 + 8) * 64 + n0] = make_float2(v10, v11);
            s0 += v10; q0 += v10 * v10;
            s1 += v11; q1 += v11 * v11;
        }
        atomicAdd(&ssum[n0], s0);     atomicAdd(&ssq[n0], q0);
        atomicAdd(&ssum[n0 + 1], s1); atomicAdd(&ssq[n0 + 1], q1);
    }
    __syncthreads();
    if (t < 64) {
        atomicAdd(&g_stats[layer * 128 + t],      ssum[t]);
        atomicAdd(&g_stats[layer * 128 + 64 + t], ssq[t]);
    }
}

// ---------------------------- BN finalize ---------------------------------
__global__ void k_bnfin(const float* __restrict__ gamma,
                        const float* __restrict__ beta, int layer, int N) {
    int t = threadIdx.x;  // 64
    if (t >= 64) return;
    float invN = 1.f / (float)N;
    float mean = g_stats[layer * 128 + t] * invN;
    float var  = g_stats[layer * 128 + 64 + t] * invN - mean * mean;
    var = fmaxf(var, 0.f);
    float s = gamma[t] * rsqrtf(var + 1e-5f);
    g_coef[layer * 128 + t]      = s;
    g_coef[layer * 128 + 64 + t] = beta[t] - mean * s;
}

// ---------------------------- pool -----------------------------------------
__global__ void k_pool(int insel /*1=g_rA, 2=g_rB*/, const int* __restrict__ batch,
                       float* __restrict__ out, int N) {
    const float* r = (insel == 1) ? g_rA : g_rB;
    const float* cf = &g_coef[2 * 128];
    int t   = threadIdx.x;  // 256
    int f   = t & 63;
    int sub = t >> 6;       // 0..3
    float a = cf[f], b = cf[64 + f];
    int n0  = blockIdx.x * 128;
    int nend = min(n0 + 128, N);
    float acc = 0.f;
    int curg = -1;
    for (int n = n0 + sub; n < nend; n += 4) {
        int g = batch[n];
        if (g != curg) {
            if (curg >= 0) atomicAdd(&out[curg * 64 + f], acc);
            curg = g;
            acc = 0.f;
        }
        acc += a * r[(size_t)n * 64 + f] + b;
    }
    if (curg >= 0) atomicAdd(&out[curg * 64 + f], acc);
}

// ---------------------------- launch ---------------------------------------
extern "C" void kernel_launch(void* const* d_in, const int* in_sizes, int n_in,
                              void* d_out, int out_size) {
    const float* x     = (const float*)d_in[0];
    const int*   ei    = (const int*)d_in[1];
    const int*   batch = (const int*)d_in[2];

    const float* WA[3] = {(const float*)d_in[3],  (const float*)d_in[9],  (const float*)d_in[15]};
    const float* BA[3] = {(const float*)d_in[4],  (const float*)d_in[10], (const float*)d_in[16]};
    const float* WB[3] = {(const float*)d_in[5],  (const float*)d_in[11], (const float*)d_in[17]};
    const float* BB[3] = {(const float*)d_in[6],  (const float*)d_in[12], (const float*)d_in[18]};
    const float* GM[3] = {(const float*)d_in[7],  (const float*)d_in[13], (const float*)d_in[19]};
    const float* BE[3] = {(const float*)d_in[8],  (const float*)d_in[14], (const float*)d_in[20]};

    int N = in_sizes[0] / 64;
    int E = in_sizes[1] / 2;
    const int* src = ei;
    const int* dst = ei + E;

    // CSR build
    k_init<<<(N + 255) / 256, 256>>>(N);
    k_hist<<<(E + 255) / 256, 256>>>(dst, E);
    int sb = (N + 1023) / 1024;
    k_scan1<<<sb, 1024>>>(N);
    k_scan2<<<1, 1024>>>(sb);
    k_scan3<<<(N + 1 + 255) / 256, 256>>>(N, E);
    k_fill<<<(E + 255) / 256, 256>>>(src, dst, E);

    // 3 GIN layers, fused gather + bf16x3 tensor-core MLP; ping-pong rA/rB
    int insel = 0;  // x
    for (int L = 0; L < 3; L++) {
        int outsel = (L & 1) ? 2 : 1;  // L0->rA, L1->rB, L2->rA
        k_fused<<<(N + 63) / 64, 256>>>(x, insel, L,
                                        WA[L], BA[L], WB[L], BB[L], outsel, N);
        k_bnfin<<<1, 64>>>(GM[L], BE[L], L, N);
        insel = outsel;
    }

    cudaMemsetAsync(d_out, 0, (size_t)out_size * sizeof(float));
    k_pool<<<(N + 127) / 128, 256>>>(insel, batch, (float*)d_out, N);
}

// round 6
// speedup vs baseline: 1.4708x; 1.0049x over previous
#include <cuda_runtime.h>
#include <cuda_bf16.h>
#include <cstdint>

// ---------------------------------------------------------------------------
// GIN encoder: 3 x (GINConv(sum-agg) -> MLP(64,relu,64) -> relu -> BN) -> add-pool
// Round 6: UN-fuse gather and MLP (the fused kernel's GEMM register state
// capped it at 2 blocks/SM and starved the latency-bound gather of warps).
//   * k_agg: 1 warp/node, ~35 regs -> high occupancy, unroll-8 => gather runs
//     at the LTS bandwidth cap. BN affine of the previous layer folded in.
//   * k_mlp: 64-node tile, bf16 m16n8k16 with 3-term compensation
//     (Ah*Bh + Ah*Bl + Al*Bh, ~2^-16/product), relu, BN stats. ~64 regs.
//   * CSR built per call; pool via sorted-batch run-length accumulation.
// ---------------------------------------------------------------------------

#define MAXN 131072
#define MAXE 2200000
#define KP   36              // smem pitch in packed (2xbf16) words

__device__ int   g_deg[MAXN];
__device__ int   g_cursor[MAXN];
__device__ int   g_rowptr[MAXN + 1];
__device__ int   g_col[MAXE];
__device__ int   g_bsum[1024];
__device__ float g_agg[(size_t)MAXN * 64];
__device__ float g_rA[(size_t)MAXN * 64];
__device__ float g_rB[(size_t)MAXN * 64];
__device__ float g_stats[3 * 128];   // per layer: [0:64) sum, [64:128) sumsq
__device__ float g_coef[3 * 128];    // per layer: [0:64) scale a, [64:128) shift b

// split (a,b) into packed bf16 hi word and lo word
__device__ __forceinline__ void bf16split2(float a, float b,
                                           uint32_t& hi, uint32_t& lo) {
    __nv_bfloat16 ha = __float2bfloat16_rn(a);
    __nv_bfloat16 hb = __float2bfloat16_rn(b);
    float la = a - __bfloat162float(ha);
    float lb = b - __bfloat162float(hb);
    __nv_bfloat162 ph, pl;
    ph.x = ha; ph.y = hb;
    pl.x = __float2bfloat16_rn(la); pl.y = __float2bfloat16_rn(lb);
    hi = *(uint32_t*)&ph;
    lo = *(uint32_t*)&pl;
}

__device__ __forceinline__ void mma_bf16(float c[4],
    uint32_t a0, uint32_t a1, uint32_t a2, uint32_t a3,
    uint32_t b0, uint32_t b1)
{
    asm volatile(
        "mma.sync.aligned.m16n8k16.row.col.f32.bf16.bf16.f32 "
        "{%0,%1,%2,%3}, {%4,%5,%6,%7}, {%8,%9}, {%0,%1,%2,%3};"
        : "+f"(c[0]), "+f"(c[1]), "+f"(c[2]), "+f"(c[3])
        : "r"(a0), "r"(a1), "r"(a2), "r"(a3), "r"(b0), "r"(b1));
}

// ---------------------------- init + CSR build ----------------------------

__global__ void k_init(int N) {
    int i = blockIdx.x * blockDim.x + threadIdx.x;
    if (i < N) { g_deg[i] = 0; g_cursor[i] = 0; }
    if (i < 384) g_stats[i] = 0.f;
}

__global__ void k_hist(const int* __restrict__ dst, int E) {
    int e = blockIdx.x * blockDim.x + threadIdx.x;
    if (e < E) atomicAdd(&g_deg[dst[e]], 1);
}

__global__ void k_scan1(int N) {
    __shared__ int wsum[32];
    int t    = threadIdx.x;            // 1024 threads
    int idx  = blockIdx.x * 1024 + t;
    int v    = (idx < N) ? g_deg[idx] : 0;
    int lane = t & 31, w = t >> 5;
    int inc  = v;
#pragma unroll
    for (int o = 1; o < 32; o <<= 1) {
        int nn = __shfl_up_sync(0xffffffffu, inc, o);
        if (lane >= o) inc += nn;
    }
    if (lane == 31) wsum[w] = inc;
    __syncthreads();
    if (w == 0) {
        int s = wsum[lane];
#pragma unroll
        for (int o = 1; o < 32; o <<= 1) {
            int nn = __shfl_up_sync(0xffffffffu, s, o);
            if (lane >= o) s += nn;
        }
        wsum[lane] = s;
    }
    __syncthreads();
    int excl = inc - v + (w > 0 ? wsum[w - 1] : 0);
    if (idx < N) g_rowptr[idx] = excl;
    if (t == 0) g_bsum[blockIdx.x] = wsum[31];
}

__global__ void k_scan2(int B) {
    __shared__ int wsum[32];
    int t    = threadIdx.x;  // 1024
    int v    = (t < B) ? g_bsum[t] : 0;
    int lane = t & 31, w = t >> 5;
    int inc  = v;
#pragma unroll
    for (int o = 1; o < 32; o <<= 1) {
        int nn = __shfl_up_sync(0xffffffffu, inc, o);
        if (lane >= o) inc += nn;
    }
    if (lane == 31) wsum[w] = inc;
    __syncthreads();
    if (w == 0) {
        int s = wsum[lane];
#pragma unroll
        for (int o = 1; o < 32; o <<= 1) {
            int nn = __shfl_up_sync(0xffffffffu, s, o);
            if (lane >= o) s += nn;
        }
        wsum[lane] = s;
    }
    __syncthreads();
    int excl = inc - v + (w > 0 ? wsum[w - 1] : 0);
    if (t < B) g_bsum[t] = excl;
}

__global__ void k_scan3(int N, int E) {
    int idx = blockIdx.x * blockDim.x + threadIdx.x;
    if (idx < N)       g_rowptr[idx] += g_bsum[idx >> 10];
    else if (idx == N) g_rowptr[N] = E;
}

__global__ void k_fill(const int* __restrict__ src, const int* __restrict__ dst, int E) {
    int e = blockIdx.x * blockDim.x + threadIdx.x;
    if (e < E) {
        int d = dst[e];
        int p = atomicAdd(&g_cursor[d], 1);
        g_col[g_rowptr[d] + p] = src[e];
    }
}

// ---------------------------- aggregation ---------------------------------
// One warp per node, float2 per lane, unroll 8 => many loads in flight.
// Previous layer's BN affine folded in: a*(self+sum) + (deg+1)*b.
__global__ __launch_bounds__(256) void k_agg(
    const float* __restrict__ x, int insel, int layer, int N)
{
    int gt   = blockIdx.x * blockDim.x + threadIdx.x;
    int node = gt >> 5;
    int lane = gt & 31;
    if (node >= N) return;

    const float* in = (insel == 0) ? x : (insel == 1 ? g_rA : g_rB);
    const float2* inp = (const float2*)in;

    int c   = node * 32 + lane;
    float2 acc = inp[c];  // self term
    int beg = g_rowptr[node], end = g_rowptr[node + 1];

    int e = beg;
    for (; e + 7 < end; e += 8) {
        int s0 = g_col[e],     s1 = g_col[e + 1];
        int s2 = g_col[e + 2], s3 = g_col[e + 3];
        int s4 = g_col[e + 4], s5 = g_col[e + 5];
        int s6 = g_col[e + 6], s7 = g_col[e + 7];
        float2 v0 = inp[s0 * 32 + lane];
        float2 v1 = inp[s1 * 32 + lane];
        float2 v2 = inp[s2 * 32 + lane];
        float2 v3 = inp[s3 * 32 + lane];
        float2 v4 = inp[s4 * 32 + lane];
        float2 v5 = inp[s5 * 32 + lane];
        float2 v6 = inp[s6 * 32 + lane];
        float2 v7 = inp[s7 * 32 + lane];
        acc.x += ((v0.x + v1.x) + (v2.x + v3.x)) + ((v4.x + v5.x) + (v6.x + v7.x));
        acc.y += ((v0.y + v1.y) + (v2.y + v3.y)) + ((v4.y + v5.y) + (v6.y + v7.y));
    }
    for (; e < end; e++) {
        float2 v = inp[g_col[e] * 32 + lane];
        acc.x += v.x;
        acc.y += v.y;
    }

    if (layer > 0) {
        const float* cf = &g_coef[(layer - 1) * 128];
        float a0 = cf[2 * lane],      a1 = cf[2 * lane + 1];
        float b0 = cf[64 + 2 * lane], b1 = cf[65 + 2 * lane];
        float cnt = (float)(end - beg + 1);
        acc.x = a0 * acc.x + cnt * b0;
        acc.y = a1 * acc.y + cnt * b1;
    }
    ((float2*)g_agg)[c] = acc;
}

// ---------- bf16x3 tensor-core MLP + relu + BN stats -----------------------
// 64-node tile per block, 256 threads (8 warps). Warp tile m16 x n32.
// Packed smem: X[row][kp] holds bf16 pair (feat 2kp, 2kp+1); pitch KP=36.
__global__ __launch_bounds__(256) void k_mlp(
    const float* __restrict__ wa, const float* __restrict__ ba,
    const float* __restrict__ wb, const float* __restrict__ bb,
    int outsel /*1=g_rA, 2=g_rB*/, int layer, int N)
{
    __shared__ uint32_t PH[64 * KP];   // A hi (agg, then h)
    __shared__ uint32_t PL[64 * KP];   // A lo
    __shared__ uint32_t QH[64 * KP];   // W hi, [n][kp]
    __shared__ uint32_t QL[64 * KP];   // W lo
    __shared__ float B1s[64], B2s[64];
    __shared__ float ssum[64], ssq[64];

    float* r = (outsel == 1) ? g_rA : g_rB;
    int t    = threadIdx.x;
    int lane = t & 31;
    int m0   = blockIdx.x * 64;

    // load W1 -> QH/QL as [n][kp]
#pragma unroll
    for (int i = 0; i < 8; i++) {
        int idx = t + 256 * i;       // 0..2047
        int n = idx & 63, kp = idx >> 6;
        uint32_t hi, lo;
        bf16split2(wa[(2 * kp) * 64 + n], wa[(2 * kp + 1) * 64 + n], hi, lo);
        QH[n * KP + kp] = hi;
        QL[n * KP + kp] = lo;
    }
    if (t < 64) { B1s[t] = ba[t]; B2s[t] = bb[t]; ssum[t] = 0.f; ssq[t] = 0.f; }

    // load A tile from g_agg (coalesced float2), split to PH/PL
#pragma unroll
    for (int i = 0; i < 8; i++) {
        int idx = t + 256 * i;       // 0..2047
        int row = idx >> 5, w = idx & 31;
        int gm = m0 + row;
        float2 v = make_float2(0.f, 0.f);
        if (gm < N) v = *(const float2*)(g_agg + (size_t)gm * 64 + 2 * w);
        uint32_t hi, lo;
        bf16split2(v.x, v.y, hi, lo);
        PH[row * KP + w] = hi;
        PL[row * KP + w] = lo;
    }
    __syncthreads();

    int gid = lane >> 2, tig = lane & 3;   // groupID, threadID-in-group
    int warp = t >> 5;
    int mi  = warp & 3,  ni  = warp >> 2;  // warp tile: rows mi*16, cols ni*32

    int aoff = (mi * 16 + gid) * KP + tig;
    int boff = (ni * 32 + gid) * KP + tig;

    float c[4][4];
#pragma unroll
    for (int nt = 0; nt < 4; nt++)
#pragma unroll
        for (int j = 0; j < 4; j++) c[nt][j] = 0.f;

    // GEMM1: 4 k-steps of 16
#pragma unroll
    for (int kt = 0; kt < 4; kt++) {
        uint32_t ah0 = PH[aoff + kt * 8];
        uint32_t ah1 = PH[aoff + kt * 8 + 8 * KP];
        uint32_t ah2 = PH[aoff + kt * 8 + 4];
        uint32_t ah3 = PH[aoff + kt * 8 + 8 * KP + 4];
        uint32_t al0 = PL[aoff + kt * 8];
        uint32_t al1 = PL[aoff + kt * 8 + 8 * KP];
        uint32_t al2 = PL[aoff + kt * 8 + 4];
        uint32_t al3 = PL[aoff + kt * 8 + 8 * KP + 4];
#pragma unroll
        for (int nt = 0; nt < 4; nt++) {
            uint32_t bh0 = QH[boff + nt * 8 * KP + kt * 8];
            uint32_t bh1 = QH[boff + nt * 8 * KP + kt * 8 + 4];
            uint32_t bl0 = QL[boff + nt * 8 * KP + kt * 8];
            uint32_t bl1 = QL[boff + nt * 8 * KP + kt * 8 + 4];
            mma_bf16(c[nt], ah0, ah1, ah2, ah3, bh0, bh1);
            mma_bf16(c[nt], ah0, ah1, ah2, ah3, bl0, bl1);
            mma_bf16(c[nt], al0, al1, al2, al3, bh0, bh1);
        }
    }
    __syncthreads();  // all reads of PH/PL (A) and QH/QL (W1) done

    // h = relu(c + b1) -> PH/PL (A of GEMM2); reload QH/QL with W2
#pragma unroll
    for (int nt = 0; nt < 4; nt++) {
        int n0 = ni * 32 + nt * 8 + 2 * tig;
        float bb0 = B1s[n0], bb1 = B1s[n0 + 1];
        int r0 = mi * 16 + gid;
        int kp = (n0 >> 1);
        uint32_t hi, lo;
        bf16split2(fmaxf(c[nt][0] + bb0, 0.f), fmaxf(c[nt][1] + bb1, 0.f), hi, lo);
        PH[r0 * KP + kp] = hi;
        PL[r0 * KP + kp] = lo;
        bf16split2(fmaxf(c[nt][2] + bb0, 0.f), fmaxf(c[nt][3] + bb1, 0.f), hi, lo);
        PH[(r0 + 8) * KP + kp] = hi;
        PL[(r0 + 8) * KP + kp] = lo;
#pragma unroll
        for (int j = 0; j < 4; j++) c[nt][j] = 0.f;
    }
#pragma unroll
    for (int i = 0; i < 8; i++) {
        int idx = t + 256 * i;
        int n = idx & 63, kp = idx >> 6;
        uint32_t hi, lo;
        bf16split2(wb[(2 * kp) * 64 + n], wb[(2 * kp + 1) * 64 + n], hi, lo);
        QH[n * KP + kp] = hi;
        QL[n * KP + kp] = lo;
    }
    __syncthreads();

    // GEMM2
#pragma unroll
    for (int kt = 0; kt < 4; kt++) {
        uint32_t ah0 = PH[aoff + kt * 8];
        uint32_t ah1 = PH[aoff + kt * 8 + 8 * KP];
        uint32_t ah2 = PH[aoff + kt * 8 + 4];
        uint32_t ah3 = PH[aoff + kt * 8 + 8 * KP + 4];
        uint32_t al0 = PL[aoff + kt * 8];
        uint32_t al1 = PL[aoff + kt * 8 + 8 * KP];
        uint32_t al2 = PL[aoff + kt * 8 + 4];
        uint32_t al3 = PL[aoff + kt * 8 + 8 * KP + 4];
#pragma unroll
        for (int nt = 0; nt < 4; nt++) {
            uint32_t bh0 = QH[boff + nt * 8 * KP + kt * 8];
            uint32_t bh1 = QH[boff + nt * 8 * KP + kt * 8 + 4];
            uint32_t bl0 = QL[boff + nt * 8 * KP + kt * 8];
            uint32_t bl1 = QL[boff + nt * 8 * KP + kt * 8 + 4];
            mma_bf16(c[nt], ah0, ah1, ah2, ah3, bh0, bh1);
            mma_bf16(c[nt], ah0, ah1, ah2, ah3, bl0, bl1);
            mma_bf16(c[nt], al0, al1, al2, al3, bh0, bh1);
        }
    }

    // epilogue: relu, store, BN stats
#pragma unroll
    for (int nt = 0; nt < 4; nt++) {
        int n0 = ni * 32 + nt * 8 + 2 * tig;
        float bb0 = B2s[n0], bb1 = B2s[n0 + 1];
        int r0 = m0 + mi * 16 + gid;
        float v00 = fmaxf(c[nt][0] + bb0, 0.f);
        float v01 = fmaxf(c[nt][1] + bb1, 0.f);
        float v10 = fmaxf(c[nt][2] + bb0, 0.f);
        float v11 = fmaxf(c[nt][3] + bb1, 0.f);
        float s0 = 0.f, q0 = 0.f, s1 = 0.f, q1 = 0.f;
        if (r0 < N) {
            *(float2*)&r[(size_t)r0 * 64 + n0] = make_float2(v00, v01);
            s0 += v00; q0 += v00 * v00;
            s1 += v01; q1 += v01 * v01;
        }
        if (r0 + 8 < N) {
            *(float2*)&r[(size_t)(r0 + 8) * 64 + n0] = make_float2(v10, v11);
            s0 += v10; q0 += v10 * v10;
            s1 += v11; q1 += v11 * v11;
        }
        atomicAdd(&ssum[n0], s0);     atomicAdd(&ssq[n0], q0);
        atomicAdd(&ssum[n0 + 1], s1); atomicAdd(&ssq[n0 + 1], q1);
    }
    __syncthreads();
    if (t < 64) {
        atomicAdd(&g_stats[layer * 128 + t],      ssum[t]);
        atomicAdd(&g_stats[layer * 128 + 64 + t], ssq[t]);
    }
}

// ---------------------------- BN finalize ---------------------------------
__global__ void k_bnfin(const float* __restrict__ gamma,
                        const float* __restrict__ beta, int layer, int N) {
    int t = threadIdx.x;  // 64
    if (t >= 64) return;
    float invN = 1.f / (float)N;
    float mean = g_stats[layer * 128 + t] * invN;
    float var  = g_stats[layer * 128 + 64 + t] * invN - mean * mean;
    var = fmaxf(var, 0.f);
    float s = gamma[t] * rsqrtf(var + 1e-5f);
    g_coef[layer * 128 + t]      = s;
    g_coef[layer * 128 + 64 + t] = beta[t] - mean * s;
}

// ---------------------------- pool -----------------------------------------
__global__ void k_pool(int insel /*1=g_rA, 2=g_rB*/, const int* __restrict__ batch,
                       float* __restrict__ out, int N) {
    const float* r = (insel == 1) ? g_rA : g_rB;
    const float* cf = &g_coef[2 * 128];
    int t   = threadIdx.x;  // 256
    int f   = t & 63;
    int sub = t >> 6;       // 0..3
    float a = cf[f], b = cf[64 + f];
    int n0  = blockIdx.x * 128;
    int nend = min(n0 + 128, N);
    float acc = 0.f;
    int curg = -1;
    for (int n = n0 + sub; n < nend; n += 4) {
        int g = batch[n];
        if (g != curg) {
            if (curg >= 0) atomicAdd(&out[curg * 64 + f], acc);
            curg = g;
            acc = 0.f;
        }
        acc += a * r[(size_t)n * 64 + f] + b;
    }
    if (curg >= 0) atomicAdd(&out[curg * 64 + f], acc);
}

// ---------------------------- launch ---------------------------------------
extern "C" void kernel_launch(void* const* d_in, const int* in_sizes, int n_in,
                              void* d_out, int out_size) {
    const float* x     = (const float*)d_in[0];
    const int*   ei    = (const int*)d_in[1];
    const int*   batch = (const int*)d_in[2];

    const float* WA[3] = {(const float*)d_in[3],  (const float*)d_in[9],  (const float*)d_in[15]};
    const float* BA[3] = {(const float*)d_in[4],  (const float*)d_in[10], (const float*)d_in[16]};
    const float* WB[3] = {(const float*)d_in[5],  (const float*)d_in[11], (const float*)d_in[17]};
    const float* BB[3] = {(const float*)d_in[6],  (const float*)d_in[12], (const float*)d_in[18]};
    const float* GM[3] = {(const float*)d_in[7],  (const float*)d_in[13], (const float*)d_in[19]};
    const float* BE[3] = {(const float*)d_in[8],  (const float*)d_in[14], (const float*)d_in[20]};

    int N = in_sizes[0] / 64;
    int E = in_sizes[1] / 2;
    const int* src = ei;
    const int* dst = ei + E;

    // CSR build
    k_init<<<(N + 255) / 256, 256>>>(N);
    k_hist<<<(E + 255) / 256, 256>>>(dst, E);
    int sb = (N + 1023) / 1024;
    k_scan1<<<sb, 1024>>>(N);
    k_scan2<<<1, 1024>>>(sb);
    k_scan3<<<(N + 1 + 255) / 256, 256>>>(N, E);
    k_fill<<<(E + 255) / 256, 256>>>(src, dst, E);

    // 3 GIN layers: high-occupancy gather, then bf16x3 tensor-core MLP
    int insel = 0;  // x
    for (int L = 0; L < 3; L++) {
        int outsel = (L & 1) ? 2 : 1;  // L0->rA, L1->rB, L2->rA
        k_agg<<<((size_t)N * 32 + 255) / 256, 256>>>(x, insel, L, N);
        k_mlp<<<(N + 63) / 64, 256>>>(WA[L], BA[L], WB[L], BB[L], outsel, L, N);
        k_bnfin<<<1, 64>>>(GM[L], BE[L], L, N);
        insel = outsel;
    }

    cudaMemsetAsync(d_out, 0, (size_t)out_size * sizeof(float));
    k_pool<<<(N + 127) / 128, 256>>>(insel, batch, (float*)d_out, N);
}